// round 8
// baseline (speedup 1.0000x reference)
#include <cuda_runtime.h>
#include <cuda_bf16.h>
#include <cstdint>

#define B_ 16
#define N_ 1024
#define D_ 768

typedef __nv_bfloat16 bf16;

static const float SCALE_ = 0.03608439182435161f; // 768^-0.5

// ---------------- scratch (device globals: allocation-free contract) ----------------
__device__ __align__(16) float g_S[(size_t)B_ * N_ * N_];   // 64 MB fp32 scores
__device__ __align__(16) float g_Q[(size_t)N_ * N_];        // 4 MB  pos softmax
__device__ __align__(16) bf16 g_xh[(size_t)B_ * N_ * D_], g_xl[(size_t)B_ * N_ * D_];
__device__ __align__(16) bf16 g_yh[(size_t)B_ * N_ * D_], g_yl[(size_t)B_ * N_ * D_];
__device__ __align__(16) bf16 g_wh[(size_t)D_ * D_],      g_wl[(size_t)D_ * D_];
__device__ __align__(16) bf16 g_kh[(size_t)B_ * N_ * D_], g_kl[(size_t)B_ * N_ * D_];
__device__ __align__(16) bf16 g_yth[(size_t)B_ * D_ * N_], g_ytl[(size_t)B_ * D_ * N_];
__device__ __align__(16) bf16 g_ah[(size_t)B_ * N_ * N_],  g_al[(size_t)B_ * N_ * N_];

// ---------------- helpers ----------------
__device__ __forceinline__ uint32_t smem_u32(const void* p) {
    uint32_t a;
    asm("{ .reg .u64 t; cvta.to.shared.u64 t, %1; cvt.u32.u64 %0, t; }" : "=r"(a) : "l"(p));
    return a;
}
#define CP_COMMIT() asm volatile("cp.async.commit_group;" ::: "memory")
#define CP_WAIT_1() asm volatile("cp.async.wait_group 1;" ::: "memory")

__device__ __forceinline__ void mma16816(float* c, const uint32_t* a, const uint32_t* b) {
    asm volatile(
        "mma.sync.aligned.m16n8k16.row.col.f32.bf16.bf16.f32 "
        "{%0,%1,%2,%3}, {%4,%5,%6,%7}, {%8,%9}, {%0,%1,%2,%3};"
        : "+f"(c[0]), "+f"(c[1]), "+f"(c[2]), "+f"(c[3])
        : "r"(a[0]), "r"(a[1]), "r"(a[2]), "r"(a[3]), "r"(b[0]), "r"(b[1]));
}
__device__ __forceinline__ void ldsm4(uint32_t* r, uint32_t addr) {
    asm volatile("ldmatrix.sync.aligned.m8n8.x4.shared.b16 {%0,%1,%2,%3}, [%4];"
        : "=r"(r[0]), "=r"(r[1]), "=r"(r[2]), "=r"(r[3]) : "r"(addr));
}

// ---------------- HMMA split-bf16 GEMM: C[M,N] = alpha * sum(A*B^T terms) ----------
// A[M,K], B[N,K] row-major, each as (hi, lo) bf16 pair. 3-term accumulation:
// Ah*Bh + Ah*Bl + Al*Bh (term-MAJOR issue order: all 32 fragments per term,
// so consecutive MMAs never share an accumulator -> no RAW stall chains).
// Block 128x128, K-chunk 32, 4 warps (warp tile 64x64). SMEM XOR-swizzled,
// 3-stage pipeline, 96 KB -> 2 CTAs/SM. Single-sync mainloop.
#define TILE_SZ 8192          // 128 * 64
#define STAGE_SZ 32768        // 4 tiles
#define NSTAGE 3
#define SMEM_BYTES (NSTAGE * STAGE_SZ)

__device__ __forceinline__ void fill_tile(uint32_t dst, const bf16* __restrict__ g,
                                          int ld, int r0, int k0, int tid) {
#pragma unroll
    for (int it = 0; it < 4; it++) {
        int idx = it * 128 + tid;
        int r = idx >> 2, b = idx & 3;
        uint32_t sw = (uint32_t)(r * 64 + ((b ^ ((r >> 1) & 3)) * 16));
        const bf16* src = g + (size_t)(r0 + r) * ld + k0 + b * 8;
        asm volatile("cp.async.cg.shared.global [%0], [%1], 16;"
                     :: "r"(dst + sw), "l"(src));
    }
}

__device__ __forceinline__ void fill_chunk(uint32_t S0,
                                           const bf16* Ah_, const bf16* Al_,
                                           const bf16* Bh_, const bf16* Bl_,
                                           int lda, int ldb, int m0, int n0, int k0, int tid) {
    fill_tile(S0 + 0 * TILE_SZ, Ah_, lda, m0, k0, tid);
    fill_tile(S0 + 1 * TILE_SZ, Al_, lda, m0, k0, tid);
    fill_tile(S0 + 2 * TILE_SZ, Bh_, ldb, n0, k0, tid);
    fill_tile(S0 + 3 * TILE_SZ, Bl_, ldb, n0, k0, tid);
}

template <bool SPLIT_OUT>
__global__ void __launch_bounds__(128, 2) gemm_mma(
    const bf16* __restrict__ Ah_, const bf16* __restrict__ Al_,
    const bf16* __restrict__ Bh_, const bf16* __restrict__ Bl_,
    float* __restrict__ C, bf16* __restrict__ Ch, bf16* __restrict__ Cl,
    int K, int lda, int ldb, int ldc,
    size_t sA, size_t sB, size_t sC, float alpha)
{
    extern __shared__ char sm[];
    const uint32_t sb = smem_u32(sm);
    const int tid = threadIdx.x, lane = tid & 31, w = tid >> 5;
    const int wm = w & 1, wn = w >> 1;          // warp grid 2(M) x 2(N)
    const int g = lane >> 2, tig = lane & 3;
    const int m0 = blockIdx.y * 128, n0 = blockIdx.x * 128;

    Ah_ += (size_t)blockIdx.z * sA; Al_ += (size_t)blockIdx.z * sA;
    Bh_ += (size_t)blockIdx.z * sB; Bl_ += (size_t)blockIdx.z * sB;

    // ldmatrix lane addressing with swizzle.
    const int rowA = wm * 64 + (lane & 7) + (lane & 8);
    const int hA = (lane >> 4) & 1;
    const int xA = (rowA >> 1) & 3;
    const uint32_t aRow = (uint32_t)(rowA * 64);
    const uint32_t aBlk0 = (uint32_t)(((0 + hA) ^ xA) * 16);
    const uint32_t aBlk1 = (uint32_t)(((2 + hA) ^ xA) * 16);
    const int rowB = wn * 64 + (lane & 7) + ((lane & 16) >> 1);
    const int hB = (lane >> 3) & 1;
    const int xB = (rowB >> 1) & 3;
    const uint32_t bRow = (uint32_t)(rowB * 64);
    const uint32_t bBlk0 = (uint32_t)(((0 + hB) ^ xB) * 16);
    const uint32_t bBlk1 = (uint32_t)(((2 + hB) ^ xB) * 16);

    float acc[4][8][4];
#pragma unroll
    for (int i = 0; i < 4; i++)
#pragma unroll
        for (int j = 0; j < 8; j++)
#pragma unroll
            for (int c = 0; c < 4; c++) acc[i][j][c] = 0.f;

    const int KT = K >> 5;

    // prologue: fill all 3 stages (chunks 0,1,2)
#pragma unroll
    for (int p = 0; p < NSTAGE; p++) {
        fill_chunk(sb + p * STAGE_SZ, Ah_, Al_, Bh_, Bl_, lda, ldb, m0, n0, p * 32, tid);
        CP_COMMIT();
    }

    for (int kt = 0; kt < KT; ++kt) {
        CP_WAIT_1();           // chunk kt resident
        __syncthreads();       // all warps finished reading stage (kt-1)%3
        if (kt >= 1) {
            if (kt + 2 < KT)
                fill_chunk(sb + ((kt + 2) % NSTAGE) * STAGE_SZ,
                           Ah_, Al_, Bh_, Bl_, lda, ldb, m0, n0, (kt + 2) * 32, tid);
            CP_COMMIT();
        }
        const uint32_t S0 = sb + (kt % NSTAGE) * STAGE_SZ;
        const uint32_t pAh = S0, pAl = S0 + TILE_SZ, pBh = S0 + 2 * TILE_SZ, pBl = S0 + 3 * TILE_SZ;

#pragma unroll
        for (int s = 0; s < 2; s++) {
            const uint32_t ab = s ? aBlk1 : aBlk0;
            const uint32_t bb = s ? bBlk1 : bBlk0;
            uint32_t ah[4][4], al[4][4], bh[8][2], bl[8][2];
#pragma unroll
            for (int mf = 0; mf < 4; mf++) {
                ldsm4(&ah[mf][0], pAh + aRow + mf * 1024 + ab);
                ldsm4(&al[mf][0], pAl + aRow + mf * 1024 + ab);
            }
#pragma unroll
            for (int p = 0; p < 4; p++) {
                ldsm4(&bh[2 * p][0], pBh + bRow + p * 1024 + bb);
                ldsm4(&bl[2 * p][0], pBl + bRow + p * 1024 + bb);
            }
            // term-major: consecutive MMAs hit different accumulators
#pragma unroll
            for (int mf = 0; mf < 4; mf++)
#pragma unroll
                for (int nf = 0; nf < 8; nf++)
                    mma16816(acc[mf][nf], ah[mf], bh[nf]);
#pragma unroll
            for (int mf = 0; mf < 4; mf++)
#pragma unroll
                for (int nf = 0; nf < 8; nf++)
                    mma16816(acc[mf][nf], ah[mf], bl[nf]);
#pragma unroll
            for (int mf = 0; mf < 4; mf++)
#pragma unroll
                for (int nf = 0; nf < 8; nf++)
                    mma16816(acc[mf][nf], al[mf], bh[nf]);
        }
    }

    // epilogue
#pragma unroll
    for (int mf = 0; mf < 4; mf++) {
#pragma unroll
        for (int nf = 0; nf < 8; nf++) {
            const int row = m0 + wm * 64 + mf * 16 + g;
            const int col = n0 + wn * 64 + nf * 8 + tig * 2;
            float c0 = acc[mf][nf][0] * alpha, c1 = acc[mf][nf][1] * alpha;
            float c2 = acc[mf][nf][2] * alpha, c3 = acc[mf][nf][3] * alpha;
            if (SPLIT_OUT) {
                bf16 h0 = __float2bfloat16_rn(c0), h1 = __float2bfloat16_rn(c1);
                bf16 h2 = __float2bfloat16_rn(c2), h3 = __float2bfloat16_rn(c3);
                bf16 l0 = __float2bfloat16_rn(c0 - __bfloat162float(h0));
                bf16 l1 = __float2bfloat16_rn(c1 - __bfloat162float(h1));
                bf16 l2 = __float2bfloat16_rn(c2 - __bfloat162float(h2));
                bf16 l3 = __float2bfloat16_rn(c3 - __bfloat162float(h3));
                bf16 ph0[2] = {h0, h1}, ph2[2] = {h2, h3};
                bf16 pl0[2] = {l0, l1}, pl2[2] = {l2, l3};
                *(uint32_t*)&Ch[(size_t)row * ldc + col]       = *(uint32_t*)ph0;
                *(uint32_t*)&Ch[(size_t)(row + 8) * ldc + col] = *(uint32_t*)ph2;
                *(uint32_t*)&Cl[(size_t)row * ldc + col]       = *(uint32_t*)pl0;
                *(uint32_t*)&Cl[(size_t)(row + 8) * ldc + col] = *(uint32_t*)pl2;
            } else {
                float* Cp = C + (size_t)blockIdx.z * sC;
                float2 v0 = {c0, c1}, v2 = {c2, c3};
                *(float2*)&Cp[(size_t)row * ldc + col]       = v0;
                *(float2*)&Cp[(size_t)(row + 8) * ldc + col] = v2;
            }
        }
    }
}

// ---------------- fp32 -> (hi,lo) bf16 split ----------------
__global__ void __launch_bounds__(256) split_k(const float4* __restrict__ in,
                                               uint2* __restrict__ hi, uint2* __restrict__ lo,
                                               int n4) {
    int i = blockIdx.x * 256 + threadIdx.x;
    if (i >= n4) return;
    float4 v = in[i];
    float xs[4] = {v.x, v.y, v.z, v.w};
    bf16 h[4], l[4];
#pragma unroll
    for (int j = 0; j < 4; j++) {
        h[j] = __float2bfloat16_rn(xs[j]);
        l[j] = __float2bfloat16_rn(xs[j] - __bfloat162float(h[j]));
    }
    hi[i] = *(uint2*)h;
    lo[i] = *(uint2*)l;
}

// ------- y [B,N,D]: split to yh/yl AND transposed yth/ytl [B,D,N] in one pass -------
__global__ void __launch_bounds__(256) split_Ty(const float* __restrict__ y,
                                                bf16* __restrict__ yh, bf16* __restrict__ yl,
                                                bf16* __restrict__ th, bf16* __restrict__ tl) {
    __shared__ float t[32][33];
    const int b = blockIdx.z;
    const float* Y = y + (size_t)b * N_ * D_;
    const int n0 = blockIdx.x * 32, d0 = blockIdx.y * 32;
    const int tx = threadIdx.x, ty = threadIdx.y;  // (32, 8)
    bf16* YH = yh + (size_t)b * N_ * D_;
    bf16* YL = yl + (size_t)b * N_ * D_;
#pragma unroll
    for (int i = 0; i < 4; i++) {
        const int r = ty + i * 8;
        const float v = Y[(size_t)(n0 + r) * D_ + d0 + tx];
        t[r][tx] = v;
        bf16 h = __float2bfloat16_rn(v);
        YH[(size_t)(n0 + r) * D_ + d0 + tx] = h;
        YL[(size_t)(n0 + r) * D_ + d0 + tx] = __float2bfloat16_rn(v - __bfloat162float(h));
    }
    __syncthreads();
    bf16* TH = th + (size_t)b * D_ * N_;
    bf16* TL = tl + (size_t)b * D_ * N_;
#pragma unroll
    for (int i = 0; i < 4; i++) {
        int r = ty + i * 8;
        float v = t[tx][r];
        bf16 h = __float2bfloat16_rn(v);
        TH[(size_t)(d0 + r) * N_ + n0 + tx] = h;
        TL[(size_t)(d0 + r) * N_ + n0 + tx] = __float2bfloat16_rn(v - __bfloat162float(h));
    }
}

// ---------------- reductions ----------------
__device__ __forceinline__ float warpMax(float v) {
#pragma unroll
    for (int o = 16; o; o >>= 1) v = fmaxf(v, __shfl_xor_sync(0xffffffffu, v, o));
    return v;
}
__device__ __forceinline__ float warpSum(float v) {
#pragma unroll
    for (int o = 16; o; o >>= 1) v += __shfl_xor_sync(0xffffffffu, v, o);
    return v;
}

// ---------------- positional softmax (SMEM-staged coalesced coords) ----------------
__global__ void __launch_bounds__(256) pos_kernel(
    const float* __restrict__ coords, const float* __restrict__ pe, float* __restrict__ Q)
{
    __shared__ float crow[N_ * 6];      // 24 KB
    __shared__ float pesh[6];
    __shared__ float red[8], red2[8];
    const int p = blockIdx.x;
    const int tid = threadIdx.x;
    if (tid < 6) pesh[tid] = pe[p * 6 + tid];

    // coalesced copy of coords row: 1536 float4s
    const float4* src = (const float4*)(coords + (size_t)p * N_ * 6);
    float4* dst = (float4*)crow;
#pragma unroll
    for (int i = 0; i < 6; i++) dst[i * 256 + tid] = src[i * 256 + tid];
    __syncthreads();

    float z[4];
#pragma unroll
    for (int i = 0; i < 4; i++) {
        const float* c = crow + (i * 256 + tid) * 6;
        z[i] = c[0] * pesh[0] + c[1] * pesh[1] + c[2] * pesh[2]
             + c[3] * pesh[3] + c[4] * pesh[4] + c[5] * pesh[5];
    }
    float m = fmaxf(fmaxf(z[0], z[1]), fmaxf(z[2], z[3]));
    m = warpMax(m);
    if ((tid & 31) == 0) red[tid >> 5] = m;
    __syncthreads();
    m = red[0];
#pragma unroll
    for (int i = 1; i < 8; i++) m = fmaxf(m, red[i]);

    float e[4], s = 0.f;
#pragma unroll
    for (int i = 0; i < 4; i++) { e[i] = expf(z[i] - m); s += e[i]; }
    s = warpSum(s);
    if ((tid & 31) == 0) red2[tid >> 5] = s;
    __syncthreads();
    s = red2[0];
#pragma unroll
    for (int i = 1; i < 8; i++) s += red2[i];
    const float inv = 1.f / s;
#pragma unroll
    for (int i = 0; i < 4; i++)
        Q[(size_t)p * N_ + i * 256 + tid] = e[i] * inv;
}

// -------- row softmax + gate mix + entropy; warp per row; attn -> bf16 hi/lo --------
__global__ void __launch_bounds__(256) mix_kernel(
    const float* __restrict__ S, const float* __restrict__ Q,
    const float* __restrict__ gating, const float* __restrict__ temp,
    bf16* __restrict__ AH, bf16* __restrict__ AL, float* __restrict__ hmap)
{
    const int row  = blockIdx.x * 8 + (threadIdx.x >> 5);   // b*N + n
    const int lane = threadIdx.x & 31;
    const float4* s4 = (const float4*)(S + (size_t)row * N_);
    const float4* q4 = (const float4*)(Q + (size_t)(row & (N_ - 1)) * N_);

    float4 v[8];
#pragma unroll
    for (int i = 0; i < 8; i++) v[i] = s4[lane + 32 * i];

    float m = -1e30f;
#pragma unroll
    for (int i = 0; i < 8; i++)
        m = fmaxf(m, fmaxf(fmaxf(v[i].x, v[i].y), fmaxf(v[i].z, v[i].w)));
    m = warpMax(m);

    float ssum = 0.f;
#pragma unroll
    for (int i = 0; i < 8; i++) {
        v[i].x = expf(v[i].x - m); v[i].y = expf(v[i].y - m);
        v[i].z = expf(v[i].z - m); v[i].w = expf(v[i].w - m);
        ssum += v[i].x + v[i].y + v[i].z + v[i].w;
    }
    ssum = warpSum(ssum);
    const float inv = 1.f / ssum;

    const float gt = 1.f / (1.f + expf(-gating[0]));
    const float og = 1.f - gt;

    uint2* AH2 = (uint2*)(AH + (size_t)row * N_);
    uint2* AL2 = (uint2*)(AL + (size_t)row * N_);
    float H = 0.f;
#pragma unroll
    for (int i = 0; i < 8; i++) {
        float4 qv = q4[lane + 32 * i];
        float a[4];
        a[0] = og * v[i].x * inv + gt * qv.x;
        a[1] = og * v[i].y * inv + gt * qv.y;
        a[2] = og * v[i].z * inv + gt * qv.z;
        a[3] = og * v[i].w * inv + gt * qv.w;
        H -= a[0] * logf(a[0] + 1e-8f) + a[1] * logf(a[1] + 1e-8f)
           + a[2] * logf(a[2] + 1e-8f) + a[3] * logf(a[3] + 1e-8f);
        bf16 h[4], l[4];
#pragma unroll
        for (int j = 0; j < 4; j++) {
            h[j] = __float2bfloat16_rn(a[j]);
            l[j] = __float2bfloat16_rn(a[j] - __bfloat162float(h[j]));
        }
        AH2[lane + 32 * i] = *(uint2*)h;
        AL2[lane + 32 * i] = *(uint2*)l;
    }
    H = warpSum(H);
    if (lane == 0) {
        const float sig = 1.f / (1.f + expf(-temp[0] * H));
        hmap[row] = 2.f * (1.f - sig);
    }
}

// ---------------- launch ----------------
extern "C" void kernel_launch(void* const* d_in, const int* in_sizes, int n_in,
                              void* d_out, int out_size)
{
    const float* x      = (const float*)d_in[0];
    const float* y      = (const float*)d_in[1];
    const float* coords = (const float*)d_in[2];
    const float* W      = (const float*)d_in[3];
    const float* pe     = (const float*)d_in[4];
    const float* gating = (const float*)d_in[5];
    const float* temp   = (const float*)d_in[6];

    float* out  = (float*)d_out;                // [B,N,D]
    float* hmap = out + (size_t)B_ * N_ * D_;   // [B,N,1]

    float *Sb, *Qb;
    bf16 *xh, *xl, *yh, *yl, *wh, *wl, *kh, *kl, *yth, *ytl, *ah, *al;
    cudaGetSymbolAddress((void**)&Sb, g_S);
    cudaGetSymbolAddress((void**)&Qb, g_Q);
    cudaGetSymbolAddress((void**)&xh, g_xh);  cudaGetSymbolAddress((void**)&xl, g_xl);
    cudaGetSymbolAddress((void**)&yh, g_yh);  cudaGetSymbolAddress((void**)&yl, g_yl);
    cudaGetSymbolAddress((void**)&wh, g_wh);  cudaGetSymbolAddress((void**)&wl, g_wl);
    cudaGetSymbolAddress((void**)&kh, g_kh);  cudaGetSymbolAddress((void**)&kl, g_kl);
    cudaGetSymbolAddress((void**)&yth, g_yth); cudaGetSymbolAddress((void**)&ytl, g_ytl);
    cudaGetSymbolAddress((void**)&ah, g_ah);  cudaGetSymbolAddress((void**)&al, g_al);

    cudaFuncSetAttribute(gemm_mma<true>,  cudaFuncAttributeMaxDynamicSharedMemorySize, SMEM_BYTES);
    cudaFuncSetAttribute(gemm_mma<false>, cudaFuncAttributeMaxDynamicSharedMemorySize, SMEM_BYTES);

    const int nBND4 = (B_ * N_ * D_) / 4;
    const int nDD4  = (D_ * D_) / 4;

    split_Ty<<<dim3(N_ / 32, D_ / 32, B_), dim3(32, 8)>>>(y, yh, yl, yth, ytl);
    split_k<<<(nBND4 + 255) / 256, 256>>>((const float4*)x, (uint2*)xh, (uint2*)xl, nBND4);
    split_k<<<(nDD4  + 255) / 256, 256>>>((const float4*)W, (uint2*)wh, (uint2*)wl, nDD4);

    pos_kernel<<<N_, 256>>>(coords, pe, Qb);

    // 1) k = y @ W^T  (M=16384, N=768, K=768) -> kh/kl bf16 directly
    gemm_mma<true><<<dim3(D_ / 128, (B_ * N_) / 128, 1), 128, SMEM_BYTES>>>(
        yh, yl, wh, wl, nullptr, kh, kl, D_, D_, D_, D_, 0, 0, 0, 1.0f);

    // 2) S = (x @ k^T) * SCALE, batched over B -> fp32
    gemm_mma<false><<<dim3(N_ / 128, N_ / 128, B_), 128, SMEM_BYTES>>>(
        xh, xl, kh, kl, Sb, nullptr, nullptr, D_, D_, D_, N_,
        (size_t)N_ * D_, (size_t)N_ * D_, (size_t)N_ * N_, SCALE_);

    // 3) softmax + mix + entropy -> attn bf16 hi/lo + hmap (warp per row)
    mix_kernel<<<(B_ * N_) / 8, 256>>>(Sb, Qb, gating, temp, ah, al, hmap);

    // 4) out = attn @ y (B operand = y^T per batch, K=1024)
    gemm_mma<false><<<dim3(D_ / 128, N_ / 128, B_), 128, SMEM_BYTES>>>(
        ah, al, yth, ytl, out, nullptr, nullptr, N_, N_, N_, D_,
        (size_t)N_ * N_, (size_t)D_ * N_, (size_t)N_ * D_, 1.0f);
}

// round 9
// speedup vs baseline: 1.0776x; 1.0776x over previous
#include <cuda_runtime.h>
#include <cuda_bf16.h>
#include <cstdint>

#define B_ 16
#define N_ 1024
#define D_ 768

typedef __nv_bfloat16 bf16;

static const float SCALE_ = 0.03608439182435161f; // 768^-0.5

// ---------------- scratch (device globals: allocation-free contract) ----------------
__device__ __align__(16) float g_S[(size_t)B_ * N_ * N_];   // 64 MB fp32 scores
__device__ __align__(16) float g_Q[(size_t)N_ * N_];        // 4 MB  pos softmax
__device__ __align__(16) bf16 g_xh[(size_t)B_ * N_ * D_], g_xl[(size_t)B_ * N_ * D_];
__device__ __align__(16) bf16 g_yh[(size_t)B_ * N_ * D_], g_yl[(size_t)B_ * N_ * D_];
__device__ __align__(16) bf16 g_wh[(size_t)D_ * D_],      g_wl[(size_t)D_ * D_];
__device__ __align__(16) bf16 g_kh[(size_t)B_ * N_ * D_], g_kl[(size_t)B_ * N_ * D_];
__device__ __align__(16) bf16 g_yth[(size_t)B_ * D_ * N_], g_ytl[(size_t)B_ * D_ * N_];
__device__ __align__(16) bf16 g_ah[(size_t)B_ * N_ * N_],  g_al[(size_t)B_ * N_ * N_];

// ---------------- helpers ----------------
__device__ __forceinline__ uint32_t smem_u32(const void* p) {
    uint32_t a;
    asm("{ .reg .u64 t; cvta.to.shared.u64 t, %1; cvt.u32.u64 %0, t; }" : "=r"(a) : "l"(p));
    return a;
}
#define CP_COMMIT() asm volatile("cp.async.commit_group;" ::: "memory")
#define CP_WAIT_1() asm volatile("cp.async.wait_group 1;" ::: "memory")

__device__ __forceinline__ void mma16816(float* c, const uint32_t* a, const uint32_t* b) {
    asm volatile(
        "mma.sync.aligned.m16n8k16.row.col.f32.bf16.bf16.f32 "
        "{%0,%1,%2,%3}, {%4,%5,%6,%7}, {%8,%9}, {%0,%1,%2,%3};"
        : "+f"(c[0]), "+f"(c[1]), "+f"(c[2]), "+f"(c[3])
        : "r"(a[0]), "r"(a[1]), "r"(a[2]), "r"(a[3]), "r"(b[0]), "r"(b[1]));
}
__device__ __forceinline__ void ldsm4(uint32_t* r, uint32_t addr) {
    asm volatile("ldmatrix.sync.aligned.m8n8.x4.shared.b16 {%0,%1,%2,%3}, [%4];"
        : "=r"(r[0]), "=r"(r[1]), "=r"(r[2]), "=r"(r[3]) : "r"(addr));
}

// ---------------- HMMA split-bf16 GEMM: C[M,N] = alpha * sum(A*B^T terms) ----------
// A[M,K], B[N,K] row-major, (hi, lo) bf16 pairs. TERMS=3: Ah*Bh + Ah*Bl + Al*Bh.
// TERMS=2: Ah*Bh + Ah*Bl (Al tile never loaded/filled -> 25% less traffic).
// Block 128x128, K-chunk 32, 4 warps (warp tile 64x64). SMEM XOR-swizzled,
// 3-stage pipeline, 96 KB -> 2 CTAs/SM. Single-sync mainloop; fills issued
// AFTER s=0 ldmatrix so fragment latency hides under MMA issue.
#define TILE_SZ 8192          // 128 * 64
#define STAGE_SZ 32768        // 4 tiles
#define NSTAGE 3
#define SMEM_BYTES (NSTAGE * STAGE_SZ)

__device__ __forceinline__ void fill_tile(uint32_t dst, const bf16* __restrict__ g,
                                          int ld, int r0, int k0, int tid) {
#pragma unroll
    for (int it = 0; it < 4; it++) {
        int idx = it * 128 + tid;
        int r = idx >> 2, b = idx & 3;
        uint32_t sw = (uint32_t)(r * 64 + ((b ^ ((r >> 1) & 3)) * 16));
        const bf16* src = g + (size_t)(r0 + r) * ld + k0 + b * 8;
        asm volatile("cp.async.cg.shared.global [%0], [%1], 16;"
                     :: "r"(dst + sw), "l"(src));
    }
}

template <int TERMS>
__device__ __forceinline__ void fill_chunk(uint32_t S0,
                                           const bf16* Ah_, const bf16* Al_,
                                           const bf16* Bh_, const bf16* Bl_,
                                           int lda, int ldb, int m0, int n0, int k0, int tid) {
    fill_tile(S0 + 0 * TILE_SZ, Ah_, lda, m0, k0, tid);
    if (TERMS == 3) fill_tile(S0 + 1 * TILE_SZ, Al_, lda, m0, k0, tid);
    fill_tile(S0 + 2 * TILE_SZ, Bh_, ldb, n0, k0, tid);
    fill_tile(S0 + 3 * TILE_SZ, Bl_, ldb, n0, k0, tid);
}

template <bool SPLIT_OUT, int TERMS>
__global__ void __launch_bounds__(128, 2) gemm_mma(
    const bf16* __restrict__ Ah_, const bf16* __restrict__ Al_,
    const bf16* __restrict__ Bh_, const bf16* __restrict__ Bl_,
    float* __restrict__ C, bf16* __restrict__ Ch, bf16* __restrict__ Cl,
    int K, int lda, int ldb, int ldc,
    size_t sA, size_t sB, size_t sC, float alpha)
{
    extern __shared__ char sm[];
    const uint32_t sb = smem_u32(sm);
    const int tid = threadIdx.x, lane = tid & 31, w = tid >> 5;
    const int wm = w & 1, wn = w >> 1;          // warp grid 2(M) x 2(N)
    const int g = lane >> 2, tig = lane & 3;
    const int m0 = blockIdx.y * 128, n0 = blockIdx.x * 128;

    Ah_ += (size_t)blockIdx.z * sA; Al_ += (size_t)blockIdx.z * sA;
    Bh_ += (size_t)blockIdx.z * sB; Bl_ += (size_t)blockIdx.z * sB;

    // ldmatrix lane addressing with swizzle.
    const int rowA = wm * 64 + (lane & 7) + (lane & 8);
    const int hA = (lane >> 4) & 1;
    const int xA = (rowA >> 1) & 3;
    const uint32_t aRow = (uint32_t)(rowA * 64);
    const uint32_t aBlk0 = (uint32_t)(((0 + hA) ^ xA) * 16);
    const uint32_t aBlk1 = (uint32_t)(((2 + hA) ^ xA) * 16);
    const int rowB = wn * 64 + (lane & 7) + ((lane & 16) >> 1);
    const int hB = (lane >> 3) & 1;
    const int xB = (rowB >> 1) & 3;
    const uint32_t bRow = (uint32_t)(rowB * 64);
    const uint32_t bBlk0 = (uint32_t)(((0 + hB) ^ xB) * 16);
    const uint32_t bBlk1 = (uint32_t)(((2 + hB) ^ xB) * 16);

    float acc[4][8][4];
#pragma unroll
    for (int i = 0; i < 4; i++)
#pragma unroll
        for (int j = 0; j < 8; j++)
#pragma unroll
            for (int c = 0; c < 4; c++) acc[i][j][c] = 0.f;

    const int KT = K >> 5;

    // prologue: fill all 3 stages (chunks 0,1,2)
#pragma unroll
    for (int p = 0; p < NSTAGE; p++) {
        fill_chunk<TERMS>(sb + p * STAGE_SZ, Ah_, Al_, Bh_, Bl_, lda, ldb, m0, n0, p * 32, tid);
        CP_COMMIT();
    }

    for (int kt = 0; kt < KT; ++kt) {
        CP_WAIT_1();           // chunk kt resident
        __syncthreads();       // all warps finished reading stage (kt-1)%3
        const uint32_t S0 = sb + (kt % NSTAGE) * STAGE_SZ;
        const uint32_t pAh = S0, pAl = S0 + TILE_SZ, pBh = S0 + 2 * TILE_SZ, pBl = S0 + 3 * TILE_SZ;

        // ---- s = 0: fragment loads FIRST (latency overlaps fill issue + MMA) ----
        uint32_t ah[4][4], al[4][4], bh[8][2], bl[8][2];
#pragma unroll
        for (int mf = 0; mf < 4; mf++) {
            ldsm4(&ah[mf][0], pAh + aRow + mf * 1024 + aBlk0);
            if (TERMS == 3) ldsm4(&al[mf][0], pAl + aRow + mf * 1024 + aBlk0);
        }
#pragma unroll
        for (int p = 0; p < 4; p++) {
            ldsm4(&bh[2 * p][0], pBh + bRow + p * 1024 + bBlk0);
            ldsm4(&bl[2 * p][0], pBl + bRow + p * 1024 + bBlk0);
        }
        // issue next-chunk fills now; they complete under the MMA shadow
        if (kt >= 1) {
            if (kt + 2 < KT)
                fill_chunk<TERMS>(sb + ((kt + 2) % NSTAGE) * STAGE_SZ,
                                  Ah_, Al_, Bh_, Bl_, lda, ldb, m0, n0, (kt + 2) * 32, tid);
            CP_COMMIT();
        }
#pragma unroll
        for (int mf = 0; mf < 4; mf++)
#pragma unroll
            for (int nf = 0; nf < 8; nf++)
                mma16816(acc[mf][nf], ah[mf], bh[nf]);
#pragma unroll
        for (int mf = 0; mf < 4; mf++)
#pragma unroll
            for (int nf = 0; nf < 8; nf++)
                mma16816(acc[mf][nf], ah[mf], bl[nf]);
        if (TERMS == 3) {
#pragma unroll
            for (int mf = 0; mf < 4; mf++)
#pragma unroll
                for (int nf = 0; nf < 8; nf++)
                    mma16816(acc[mf][nf], al[mf], bh[nf]);
        }

        // ---- s = 1 ----
#pragma unroll
        for (int mf = 0; mf < 4; mf++) {
            ldsm4(&ah[mf][0], pAh + aRow + mf * 1024 + aBlk1);
            if (TERMS == 3) ldsm4(&al[mf][0], pAl + aRow + mf * 1024 + aBlk1);
        }
#pragma unroll
        for (int p = 0; p < 4; p++) {
            ldsm4(&bh[2 * p][0], pBh + bRow + p * 1024 + bBlk1);
            ldsm4(&bl[2 * p][0], pBl + bRow + p * 1024 + bBlk1);
        }
#pragma unroll
        for (int mf = 0; mf < 4; mf++)
#pragma unroll
            for (int nf = 0; nf < 8; nf++)
                mma16816(acc[mf][nf], ah[mf], bh[nf]);
#pragma unroll
        for (int mf = 0; mf < 4; mf++)
#pragma unroll
            for (int nf = 0; nf < 8; nf++)
                mma16816(acc[mf][nf], ah[mf], bl[nf]);
        if (TERMS == 3) {
#pragma unroll
            for (int mf = 0; mf < 4; mf++)
#pragma unroll
                for (int nf = 0; nf < 8; nf++)
                    mma16816(acc[mf][nf], al[mf], bh[nf]);
        }
    }

    // epilogue
#pragma unroll
    for (int mf = 0; mf < 4; mf++) {
#pragma unroll
        for (int nf = 0; nf < 8; nf++) {
            const int row = m0 + wm * 64 + mf * 16 + g;
            const int col = n0 + wn * 64 + nf * 8 + tig * 2;
            float c0 = acc[mf][nf][0] * alpha, c1 = acc[mf][nf][1] * alpha;
            float c2 = acc[mf][nf][2] * alpha, c3 = acc[mf][nf][3] * alpha;
            if (SPLIT_OUT) {
                bf16 h0 = __float2bfloat16_rn(c0), h1 = __float2bfloat16_rn(c1);
                bf16 h2 = __float2bfloat16_rn(c2), h3 = __float2bfloat16_rn(c3);
                bf16 l0 = __float2bfloat16_rn(c0 - __bfloat162float(h0));
                bf16 l1 = __float2bfloat16_rn(c1 - __bfloat162float(h1));
                bf16 l2 = __float2bfloat16_rn(c2 - __bfloat162float(h2));
                bf16 l3 = __float2bfloat16_rn(c3 - __bfloat162float(h3));
                bf16 ph0[2] = {h0, h1}, ph2[2] = {h2, h3};
                bf16 pl0[2] = {l0, l1}, pl2[2] = {l2, l3};
                *(uint32_t*)&Ch[(size_t)row * ldc + col]       = *(uint32_t*)ph0;
                *(uint32_t*)&Ch[(size_t)(row + 8) * ldc + col] = *(uint32_t*)ph2;
                *(uint32_t*)&Cl[(size_t)row * ldc + col]       = *(uint32_t*)pl0;
                *(uint32_t*)&Cl[(size_t)(row + 8) * ldc + col] = *(uint32_t*)pl2;
            } else {
                float* Cp = C + (size_t)blockIdx.z * sC;
                float2 v0 = {c0, c1}, v2 = {c2, c3};
                *(float2*)&Cp[(size_t)row * ldc + col]       = v0;
                *(float2*)&Cp[(size_t)(row + 8) * ldc + col] = v2;
            }
        }
    }
}

// ---------------- fp32 -> (hi,lo) bf16 split ----------------
__global__ void __launch_bounds__(256) split_k(const float4* __restrict__ in,
                                               uint2* __restrict__ hi, uint2* __restrict__ lo,
                                               int n4) {
    int i = blockIdx.x * 256 + threadIdx.x;
    if (i >= n4) return;
    float4 v = in[i];
    float xs[4] = {v.x, v.y, v.z, v.w};
    bf16 h[4], l[4];
#pragma unroll
    for (int j = 0; j < 4; j++) {
        h[j] = __float2bfloat16_rn(xs[j]);
        l[j] = __float2bfloat16_rn(xs[j] - __bfloat162float(h[j]));
    }
    hi[i] = *(uint2*)h;
    lo[i] = *(uint2*)l;
}

// ------- y [B,N,D]: split to yh/yl AND transposed yth/ytl [B,D,N] in one pass -------
__global__ void __launch_bounds__(256) split_Ty(const float* __restrict__ y,
                                                bf16* __restrict__ yh, bf16* __restrict__ yl,
                                                bf16* __restrict__ th, bf16* __restrict__ tl) {
    __shared__ float t[32][33];
    const int b = blockIdx.z;
    const float* Y = y + (size_t)b * N_ * D_;
    const int n0 = blockIdx.x * 32, d0 = blockIdx.y * 32;
    const int tx = threadIdx.x, ty = threadIdx.y;  // (32, 8)
    bf16* YH = yh + (size_t)b * N_ * D_;
    bf16* YL = yl + (size_t)b * N_ * D_;
#pragma unroll
    for (int i = 0; i < 4; i++) {
        const int r = ty + i * 8;
        const float v = Y[(size_t)(n0 + r) * D_ + d0 + tx];
        t[r][tx] = v;
        bf16 h = __float2bfloat16_rn(v);
        YH[(size_t)(n0 + r) * D_ + d0 + tx] = h;
        YL[(size_t)(n0 + r) * D_ + d0 + tx] = __float2bfloat16_rn(v - __bfloat162float(h));
    }
    __syncthreads();
    bf16* TH = th + (size_t)b * D_ * N_;
    bf16* TL = tl + (size_t)b * D_ * N_;
#pragma unroll
    for (int i = 0; i < 4; i++) {
        int r = ty + i * 8;
        float v = t[tx][r];
        bf16 h = __float2bfloat16_rn(v);
        TH[(size_t)(d0 + r) * N_ + n0 + tx] = h;
        TL[(size_t)(d0 + r) * N_ + n0 + tx] = __float2bfloat16_rn(v - __bfloat162float(h));
    }
}

// ---------------- reductions ----------------
__device__ __forceinline__ float warpMax(float v) {
#pragma unroll
    for (int o = 16; o; o >>= 1) v = fmaxf(v, __shfl_xor_sync(0xffffffffu, v, o));
    return v;
}
__device__ __forceinline__ float warpSum(float v) {
#pragma unroll
    for (int o = 16; o; o >>= 1) v += __shfl_xor_sync(0xffffffffu, v, o);
    return v;
}

// ---------------- positional softmax ----------------
__global__ void __launch_bounds__(256) pos_kernel(
    const float* __restrict__ coords, const float* __restrict__ pe, float* __restrict__ Q)
{
    __shared__ float pesh[6];
    __shared__ float red[8], red2[8];
    const int p = blockIdx.x;
    const int tid = threadIdx.x;
    if (tid < 6) pesh[tid] = pe[p * 6 + tid];
    __syncthreads();

    const float* cbase = coords + (size_t)p * N_ * 6;
    float z[4];
#pragma unroll
    for (int i = 0; i < 4; i++) {
        const float* c = cbase + (size_t)(i * 256 + tid) * 6;
        z[i] = c[0] * pesh[0] + c[1] * pesh[1] + c[2] * pesh[2]
             + c[3] * pesh[3] + c[4] * pesh[4] + c[5] * pesh[5];
    }
    float m = fmaxf(fmaxf(z[0], z[1]), fmaxf(z[2], z[3]));
    m = warpMax(m);
    if ((tid & 31) == 0) red[tid >> 5] = m;
    __syncthreads();
    m = red[0];
#pragma unroll
    for (int i = 1; i < 8; i++) m = fmaxf(m, red[i]);

    float e[4], s = 0.f;
#pragma unroll
    for (int i = 0; i < 4; i++) { e[i] = expf(z[i] - m); s += e[i]; }
    s = warpSum(s);
    if ((tid & 31) == 0) red2[tid >> 5] = s;
    __syncthreads();
    s = red2[0];
#pragma unroll
    for (int i = 1; i < 8; i++) s += red2[i];
    const float inv = 1.f / s;
#pragma unroll
    for (int i = 0; i < 4; i++)
        Q[(size_t)p * N_ + i * 256 + tid] = e[i] * inv;
}

// -------- row softmax + gate mix + entropy; warp per row; attn -> bf16 hi/lo --------
__global__ void __launch_bounds__(256) mix_kernel(
    const float* __restrict__ S, const float* __restrict__ Q,
    const float* __restrict__ gating, const float* __restrict__ temp,
    bf16* __restrict__ AH, bf16* __restrict__ AL, float* __restrict__ hmap)
{
    const int row  = blockIdx.x * 8 + (threadIdx.x >> 5);   // b*N + n
    const int lane = threadIdx.x & 31;
    const float4* s4 = (const float4*)(S + (size_t)row * N_);
    const float4* q4 = (const float4*)(Q + (size_t)(row & (N_ - 1)) * N_);

    float4 v[8];
#pragma unroll
    for (int i = 0; i < 8; i++) v[i] = s4[lane + 32 * i];

    float m = -1e30f;
#pragma unroll
    for (int i = 0; i < 8; i++)
        m = fmaxf(m, fmaxf(fmaxf(v[i].x, v[i].y), fmaxf(v[i].z, v[i].w)));
    m = warpMax(m);

    float ssum = 0.f;
#pragma unroll
    for (int i = 0; i < 8; i++) {
        v[i].x = expf(v[i].x - m); v[i].y = expf(v[i].y - m);
        v[i].z = expf(v[i].z - m); v[i].w = expf(v[i].w - m);
        ssum += v[i].x + v[i].y + v[i].z + v[i].w;
    }
    ssum = warpSum(ssum);
    const float inv = 1.f / ssum;

    const float gt = 1.f / (1.f + expf(-gating[0]));
    const float og = 1.f - gt;

    uint2* AH2 = (uint2*)(AH + (size_t)row * N_);
    uint2* AL2 = (uint2*)(AL + (size_t)row * N_);
    float H = 0.f;
#pragma unroll
    for (int i = 0; i < 8; i++) {
        float4 qv = q4[lane + 32 * i];
        float a[4];
        a[0] = og * v[i].x * inv + gt * qv.x;
        a[1] = og * v[i].y * inv + gt * qv.y;
        a[2] = og * v[i].z * inv + gt * qv.z;
        a[3] = og * v[i].w * inv + gt * qv.w;
        H -= a[0] * logf(a[0] + 1e-8f) + a[1] * logf(a[1] + 1e-8f)
           + a[2] * logf(a[2] + 1e-8f) + a[3] * logf(a[3] + 1e-8f);
        bf16 h[4], l[4];
#pragma unroll
        for (int j = 0; j < 4; j++) {
            h[j] = __float2bfloat16_rn(a[j]);
            l[j] = __float2bfloat16_rn(a[j] - __bfloat162float(h[j]));
        }
        AH2[lane + 32 * i] = *(uint2*)h;
        AL2[lane + 32 * i] = *(uint2*)l;
    }
    H = warpSum(H);
    if (lane == 0) {
        const float sig = 1.f / (1.f + expf(-temp[0] * H));
        hmap[row] = 2.f * (1.f - sig);
    }
}

// ---------------- launch ----------------
extern "C" void kernel_launch(void* const* d_in, const int* in_sizes, int n_in,
                              void* d_out, int out_size)
{
    const float* x      = (const float*)d_in[0];
    const float* y      = (const float*)d_in[1];
    const float* coords = (const float*)d_in[2];
    const float* W      = (const float*)d_in[3];
    const float* pe     = (const float*)d_in[4];
    const float* gating = (const float*)d_in[5];
    const float* temp   = (const float*)d_in[6];

    float* out  = (float*)d_out;                // [B,N,D]
    float* hmap = out + (size_t)B_ * N_ * D_;   // [B,N,1]

    float *Sb, *Qb;
    bf16 *xh, *xl, *yh, *yl, *wh, *wl, *kh, *kl, *yth, *ytl, *ah, *al;
    cudaGetSymbolAddress((void**)&Sb, g_S);
    cudaGetSymbolAddress((void**)&Qb, g_Q);
    cudaGetSymbolAddress((void**)&xh, g_xh);  cudaGetSymbolAddress((void**)&xl, g_xl);
    cudaGetSymbolAddress((void**)&yh, g_yh);  cudaGetSymbolAddress((void**)&yl, g_yl);
    cudaGetSymbolAddress((void**)&wh, g_wh);  cudaGetSymbolAddress((void**)&wl, g_wl);
    cudaGetSymbolAddress((void**)&kh, g_kh);  cudaGetSymbolAddress((void**)&kl, g_kl);
    cudaGetSymbolAddress((void**)&yth, g_yth); cudaGetSymbolAddress((void**)&ytl, g_ytl);
    cudaGetSymbolAddress((void**)&ah, g_ah);  cudaGetSymbolAddress((void**)&al, g_al);

    cudaFuncSetAttribute((const void*)gemm_mma<true, 3>,  cudaFuncAttributeMaxDynamicSharedMemorySize, SMEM_BYTES);
    cudaFuncSetAttribute((const void*)gemm_mma<false, 2>, cudaFuncAttributeMaxDynamicSharedMemorySize, SMEM_BYTES);
    cudaFuncSetAttribute((const void*)gemm_mma<false, 3>, cudaFuncAttributeMaxDynamicSharedMemorySize, SMEM_BYTES);

    const int nBND4 = (B_ * N_ * D_) / 4;
    const int nDD4  = (D_ * D_) / 4;

    split_Ty<<<dim3(N_ / 32, D_ / 32, B_), dim3(32, 8)>>>(y, yh, yl, yth, ytl);
    split_k<<<(nBND4 + 255) / 256, 256>>>((const float4*)x, (uint2*)xh, (uint2*)xl, nBND4);
    split_k<<<(nDD4  + 255) / 256, 256>>>((const float4*)W, (uint2*)wh, (uint2*)wl, nDD4);

    pos_kernel<<<N_, 256>>>(coords, pe, Qb);

    // 1) k = y @ W^T  (M=16384, N=768, K=768) -> kh/kl bf16 directly (3-term)
    gemm_mma<true, 3><<<dim3(D_ / 128, (B_ * N_) / 128, 1), 128, SMEM_BYTES>>>(
        yh, yl, wh, wl, nullptr, kh, kl, D_, D_, D_, D_, 0, 0, 0, 1.0f);

    // 2) S = (x @ k^T) * SCALE, batched over B -> fp32 (2-term: scores feed softmax)
    gemm_mma<false, 2><<<dim3(N_ / 128, N_ / 128, B_), 128, SMEM_BYTES>>>(
        xh, xl, kh, kl, Sb, nullptr, nullptr, D_, D_, D_, N_,
        (size_t)N_ * D_, (size_t)N_ * D_, (size_t)N_ * N_, SCALE_);

    // 3) softmax + mix + entropy -> attn bf16 hi/lo + hmap (warp per row)
    mix_kernel<<<(B_ * N_) / 8, 256>>>(Sb, Qb, gating, temp, ah, al, hmap);

    // 4) out = attn @ y (B operand = y^T per batch, K=1024) (3-term: direct output)
    gemm_mma<false, 3><<<dim3(D_ / 128, N_ / 128, B_), 128, SMEM_BYTES>>>(
        ah, al, yth, ytl, out, nullptr, nullptr, N_, N_, N_, D_,
        (size_t)N_ * N_, (size_t)D_ * N_, (size_t)N_ * D_, 1.0f);
}

// round 10
// speedup vs baseline: 1.0832x; 1.0053x over previous
#include <cuda_runtime.h>
#include <cuda_bf16.h>
#include <cstdint>

#define B_ 16
#define N_ 1024
#define D_ 768

typedef __nv_bfloat16 bf16;

static const float SCALE_ = 0.03608439182435161f; // 768^-0.5

// ---------------- scratch (device globals: allocation-free contract) ----------------
__device__ __align__(16) float g_S[(size_t)B_ * N_ * N_];   // 64 MB fp32 scores
__device__ __align__(16) float g_Q[(size_t)N_ * N_];        // 4 MB  pos softmax
__device__ __align__(16) bf16 g_xh[(size_t)B_ * N_ * D_];
__device__ __align__(16) bf16 g_yh[(size_t)B_ * N_ * D_], g_yl[(size_t)B_ * N_ * D_];
__device__ __align__(16) bf16 g_wh[(size_t)D_ * D_],      g_wl[(size_t)D_ * D_];
__device__ __align__(16) bf16 g_kh[(size_t)B_ * N_ * D_], g_kl[(size_t)B_ * N_ * D_];
__device__ __align__(16) bf16 g_yth[(size_t)B_ * D_ * N_], g_ytl[(size_t)B_ * D_ * N_];
__device__ __align__(16) bf16 g_ah[(size_t)B_ * N_ * N_],  g_al[(size_t)B_ * N_ * N_];

// ---------------- helpers ----------------
__device__ __forceinline__ uint32_t smem_u32(const void* p) {
    uint32_t a;
    asm("{ .reg .u64 t; cvta.to.shared.u64 t, %1; cvt.u32.u64 %0, t; }" : "=r"(a) : "l"(p));
    return a;
}
#define CP_COMMIT() asm volatile("cp.async.commit_group;" ::: "memory")

__device__ __forceinline__ void mma16816(float* c, const uint32_t* a, const uint32_t* b) {
    asm volatile(
        "mma.sync.aligned.m16n8k16.row.col.f32.bf16.bf16.f32 "
        "{%0,%1,%2,%3}, {%4,%5,%6,%7}, {%8,%9}, {%0,%1,%2,%3};"
        : "+f"(c[0]), "+f"(c[1]), "+f"(c[2]), "+f"(c[3])
        : "r"(a[0]), "r"(a[1]), "r"(a[2]), "r"(a[3]), "r"(b[0]), "r"(b[1]));
}
__device__ __forceinline__ void ldsm4(uint32_t* r, uint32_t addr) {
    asm volatile("ldmatrix.sync.aligned.m8n8.x4.shared.b16 {%0,%1,%2,%3}, [%4];"
        : "=r"(r[0]), "=r"(r[1]), "=r"(r[2]), "=r"(r[3]) : "r"(addr));
}

// ---------------- HMMA split-bf16 GEMM: C[M,N] = alpha * sum(A*B^T terms) ----------
// A[M,K], B[N,K] row-major, (hi, lo) bf16 pairs. TERMS=3: Ah*Bh + Ah*Bl + Al*Bh
//   (4 tiles/stage, 3 stages). TERMS=2: Ah*Bh + Ah*Bl, Al never touched
//   (compact 3 tiles/stage, 4 stages). Both use 96 KB -> 2 CTAs/SM.
// Block 128x128, K-chunk 32, 4 warps (warp tile 64x64). SMEM XOR-swizzled.
// Single-sync mainloop; fills issued AFTER s=0 ldmatrix.
#define TILE_SZ 8192          // 128 * 64
#define SMEM_BYTES 98304      // 96 KB (both variants)

__device__ __forceinline__ void fill_tile(uint32_t dst, const bf16* __restrict__ g,
                                          int ld, int r0, int k0, int tid) {
#pragma unroll
    for (int it = 0; it < 4; it++) {
        int idx = it * 128 + tid;
        int r = idx >> 2, b = idx & 3;
        uint32_t sw = (uint32_t)(r * 64 + ((b ^ ((r >> 1) & 3)) * 16));
        const bf16* src = g + (size_t)(r0 + r) * ld + k0 + b * 8;
        asm volatile("cp.async.cg.shared.global [%0], [%1], 16;"
                     :: "r"(dst + sw), "l"(src));
    }
}

template <int TERMS>
__device__ __forceinline__ void fill_chunk(uint32_t S0,
                                           const bf16* Ah_, const bf16* Al_,
                                           const bf16* Bh_, const bf16* Bl_,
                                           int lda, int ldb, int m0, int n0, int k0, int tid) {
    constexpr int BH = (TERMS == 3) ? 2 : 1;
    fill_tile(S0 + 0 * TILE_SZ, Ah_, lda, m0, k0, tid);
    if (TERMS == 3) fill_tile(S0 + 1 * TILE_SZ, Al_, lda, m0, k0, tid);
    fill_tile(S0 + BH * TILE_SZ,       Bh_, ldb, n0, k0, tid);
    fill_tile(S0 + (BH + 1) * TILE_SZ, Bl_, ldb, n0, k0, tid);
}

template <bool SPLIT_OUT, int TERMS>
__global__ void __launch_bounds__(128, 2) gemm_mma(
    const bf16* __restrict__ Ah_, const bf16* __restrict__ Al_,
    const bf16* __restrict__ Bh_, const bf16* __restrict__ Bl_,
    float* __restrict__ C, bf16* __restrict__ Ch, bf16* __restrict__ Cl,
    int K, int lda, int ldb, int ldc,
    size_t sA, size_t sB, size_t sC, float alpha)
{
    constexpr int NST = (TERMS == 3) ? 3 : 4;
    constexpr int STG = ((TERMS == 3) ? 4 : 3) * TILE_SZ;
    constexpr int BH  = (TERMS == 3) ? 2 : 1;

    extern __shared__ char sm[];
    const uint32_t sb = smem_u32(sm);
    const int tid = threadIdx.x, lane = tid & 31, w = tid >> 5;
    const int wm = w & 1, wn = w >> 1;          // warp grid 2(M) x 2(N)
    const int g = lane >> 2, tig = lane & 3;
    const int m0 = blockIdx.y * 128, n0 = blockIdx.x * 128;

    Ah_ += (size_t)blockIdx.z * sA; Al_ += (size_t)blockIdx.z * sA;
    Bh_ += (size_t)blockIdx.z * sB; Bl_ += (size_t)blockIdx.z * sB;

    // ldmatrix lane addressing with swizzle.
    const int rowA = wm * 64 + (lane & 7) + (lane & 8);
    const int hA = (lane >> 4) & 1;
    const int xA = (rowA >> 1) & 3;
    const uint32_t aRow = (uint32_t)(rowA * 64);
    const uint32_t aBlk0 = (uint32_t)(((0 + hA) ^ xA) * 16);
    const uint32_t aBlk1 = (uint32_t)(((2 + hA) ^ xA) * 16);
    const int rowB = wn * 64 + (lane & 7) + ((lane & 16) >> 1);
    const int hB = (lane >> 3) & 1;
    const int xB = (rowB >> 1) & 3;
    const uint32_t bRow = (uint32_t)(rowB * 64);
    const uint32_t bBlk0 = (uint32_t)(((0 + hB) ^ xB) * 16);
    const uint32_t bBlk1 = (uint32_t)(((2 + hB) ^ xB) * 16);

    float acc[4][8][4];
#pragma unroll
    for (int i = 0; i < 4; i++)
#pragma unroll
        for (int j = 0; j < 8; j++)
#pragma unroll
            for (int c = 0; c < 4; c++) acc[i][j][c] = 0.f;

    const int KT = K >> 5;

    // prologue: fill all NST stages (chunks 0..NST-1)
#pragma unroll
    for (int p = 0; p < NST; p++) {
        fill_chunk<TERMS>(sb + p * STG, Ah_, Al_, Bh_, Bl_, lda, ldb, m0, n0, p * 32, tid);
        CP_COMMIT();
    }

    for (int kt = 0; kt < KT; ++kt) {
        // chunk kt complete when <= NST-2 groups outstanding
        asm volatile("cp.async.wait_group %0;" :: "n"(NST - 2) : "memory");
        __syncthreads();       // all warps finished reading stage (kt-1)%NST
        const uint32_t S0 = sb + (kt % NST) * STG;
        const uint32_t pAh = S0, pAl = S0 + TILE_SZ;
        const uint32_t pBh = S0 + BH * TILE_SZ, pBl = S0 + (BH + 1) * TILE_SZ;

        // ---- s = 0: fragment loads FIRST ----
        uint32_t ah[4][4], al[4][4], bh[8][2], bl[8][2];
#pragma unroll
        for (int mf = 0; mf < 4; mf++) {
            ldsm4(&ah[mf][0], pAh + aRow + mf * 1024 + aBlk0);
            if (TERMS == 3) ldsm4(&al[mf][0], pAl + aRow + mf * 1024 + aBlk0);
        }
#pragma unroll
        for (int p = 0; p < 4; p++) {
            ldsm4(&bh[2 * p][0], pBh + bRow + p * 1024 + bBlk0);
            ldsm4(&bl[2 * p][0], pBl + bRow + p * 1024 + bBlk0);
        }
        // issue next-chunk fills now; they complete under the MMA shadow
        if (kt >= 1) {
            if (kt + NST - 1 < KT)
                fill_chunk<TERMS>(sb + ((kt + NST - 1) % NST) * STG,
                                  Ah_, Al_, Bh_, Bl_, lda, ldb, m0, n0,
                                  (kt + NST - 1) * 32, tid);
            CP_COMMIT();
        }
#pragma unroll
        for (int mf = 0; mf < 4; mf++)
#pragma unroll
            for (int nf = 0; nf < 8; nf++)
                mma16816(acc[mf][nf], ah[mf], bh[nf]);
#pragma unroll
        for (int mf = 0; mf < 4; mf++)
#pragma unroll
            for (int nf = 0; nf < 8; nf++)
                mma16816(acc[mf][nf], ah[mf], bl[nf]);
        if (TERMS == 3) {
#pragma unroll
            for (int mf = 0; mf < 4; mf++)
#pragma unroll
                for (int nf = 0; nf < 8; nf++)
                    mma16816(acc[mf][nf], al[mf], bh[nf]);
        }

        // ---- s = 1 ----
#pragma unroll
        for (int mf = 0; mf < 4; mf++) {
            ldsm4(&ah[mf][0], pAh + aRow + mf * 1024 + aBlk1);
            if (TERMS == 3) ldsm4(&al[mf][0], pAl + aRow + mf * 1024 + aBlk1);
        }
#pragma unroll
        for (int p = 0; p < 4; p++) {
            ldsm4(&bh[2 * p][0], pBh + bRow + p * 1024 + bBlk1);
            ldsm4(&bl[2 * p][0], pBl + bRow + p * 1024 + bBlk1);
        }
#pragma unroll
        for (int mf = 0; mf < 4; mf++)
#pragma unroll
            for (int nf = 0; nf < 8; nf++)
                mma16816(acc[mf][nf], ah[mf], bh[nf]);
#pragma unroll
        for (int mf = 0; mf < 4; mf++)
#pragma unroll
            for (int nf = 0; nf < 8; nf++)
                mma16816(acc[mf][nf], ah[mf], bl[nf]);
        if (TERMS == 3) {
#pragma unroll
            for (int mf = 0; mf < 4; mf++)
#pragma unroll
                for (int nf = 0; nf < 8; nf++)
                    mma16816(acc[mf][nf], al[mf], bh[nf]);
        }
    }

    // epilogue
#pragma unroll
    for (int mf = 0; mf < 4; mf++) {
#pragma unroll
        for (int nf = 0; nf < 8; nf++) {
            const int row = m0 + wm * 64 + mf * 16 + g;
            const int col = n0 + wn * 64 + nf * 8 + tig * 2;
            float c0 = acc[mf][nf][0] * alpha, c1 = acc[mf][nf][1] * alpha;
            float c2 = acc[mf][nf][2] * alpha, c3 = acc[mf][nf][3] * alpha;
            if (SPLIT_OUT) {
                bf16 h0 = __float2bfloat16_rn(c0), h1 = __float2bfloat16_rn(c1);
                bf16 h2 = __float2bfloat16_rn(c2), h3 = __float2bfloat16_rn(c3);
                bf16 l0 = __float2bfloat16_rn(c0 - __bfloat162float(h0));
                bf16 l1 = __float2bfloat16_rn(c1 - __bfloat162float(h1));
                bf16 l2 = __float2bfloat16_rn(c2 - __bfloat162float(h2));
                bf16 l3 = __float2bfloat16_rn(c3 - __bfloat162float(h3));
                bf16 ph0[2] = {h0, h1}, ph2[2] = {h2, h3};
                bf16 pl0[2] = {l0, l1}, pl2[2] = {l2, l3};
                *(uint32_t*)&Ch[(size_t)row * ldc + col]       = *(uint32_t*)ph0;
                *(uint32_t*)&Ch[(size_t)(row + 8) * ldc + col] = *(uint32_t*)ph2;
                *(uint32_t*)&Cl[(size_t)row * ldc + col]       = *(uint32_t*)pl0;
                *(uint32_t*)&Cl[(size_t)(row + 8) * ldc + col] = *(uint32_t*)pl2;
            } else {
                float* Cp = C + (size_t)blockIdx.z * sC;
                float2 v0 = {c0, c1}, v2 = {c2, c3};
                *(float2*)&Cp[(size_t)row * ldc + col]       = v0;
                *(float2*)&Cp[(size_t)(row + 8) * ldc + col] = v2;
            }
        }
    }
}

// ---------------- fp32 -> (hi,lo) bf16 split ----------------
__global__ void __launch_bounds__(256) split_k(const float4* __restrict__ in,
                                               uint2* __restrict__ hi, uint2* __restrict__ lo,
                                               int n4) {
    int i = blockIdx.x * 256 + threadIdx.x;
    if (i >= n4) return;
    float4 v = in[i];
    float xs[4] = {v.x, v.y, v.z, v.w};
    bf16 h[4], l[4];
#pragma unroll
    for (int j = 0; j < 4; j++) {
        h[j] = __float2bfloat16_rn(xs[j]);
        l[j] = __float2bfloat16_rn(xs[j] - __bfloat162float(h[j]));
    }
    hi[i] = *(uint2*)h;
    lo[i] = *(uint2*)l;
}

// ---------------- fp32 -> hi bf16 only (lo term unused downstream) ----------------
__global__ void __launch_bounds__(256) split_h(const float4* __restrict__ in,
                                               uint2* __restrict__ hi, int n4) {
    int i = blockIdx.x * 256 + threadIdx.x;
    if (i >= n4) return;
    float4 v = in[i];
    float xs[4] = {v.x, v.y, v.z, v.w};
    bf16 h[4];
#pragma unroll
    for (int j = 0; j < 4; j++) h[j] = __float2bfloat16_rn(xs[j]);
    hi[i] = *(uint2*)h;
}

// ------- y [B,N,D]: split to yh/yl AND transposed yth/ytl [B,D,N] in one pass -------
__global__ void __launch_bounds__(256) split_Ty(const float* __restrict__ y,
                                                bf16* __restrict__ yh, bf16* __restrict__ yl,
                                                bf16* __restrict__ th, bf16* __restrict__ tl) {
    __shared__ float t[32][33];
    const int b = blockIdx.z;
    const float* Y = y + (size_t)b * N_ * D_;
    const int n0 = blockIdx.x * 32, d0 = blockIdx.y * 32;
    const int tx = threadIdx.x, ty = threadIdx.y;  // (32, 8)
    bf16* YH = yh + (size_t)b * N_ * D_;
    bf16* YL = yl + (size_t)b * N_ * D_;
#pragma unroll
    for (int i = 0; i < 4; i++) {
        const int r = ty + i * 8;
        const float v = Y[(size_t)(n0 + r) * D_ + d0 + tx];
        t[r][tx] = v;
        bf16 h = __float2bfloat16_rn(v);
        YH[(size_t)(n0 + r) * D_ + d0 + tx] = h;
        YL[(size_t)(n0 + r) * D_ + d0 + tx] = __float2bfloat16_rn(v - __bfloat162float(h));
    }
    __syncthreads();
    bf16* TH = th + (size_t)b * D_ * N_;
    bf16* TL = tl + (size_t)b * D_ * N_;
#pragma unroll
    for (int i = 0; i < 4; i++) {
        int r = ty + i * 8;
        float v = t[tx][r];
        bf16 h = __float2bfloat16_rn(v);
        TH[(size_t)(d0 + r) * N_ + n0 + tx] = h;
        TL[(size_t)(d0 + r) * N_ + n0 + tx] = __float2bfloat16_rn(v - __bfloat162float(h));
    }
}

// ---------------- reductions ----------------
__device__ __forceinline__ float warpMax(float v) {
#pragma unroll
    for (int o = 16; o; o >>= 1) v = fmaxf(v, __shfl_xor_sync(0xffffffffu, v, o));
    return v;
}
__device__ __forceinline__ float warpSum(float v) {
#pragma unroll
    for (int o = 16; o; o >>= 1) v += __shfl_xor_sync(0xffffffffu, v, o);
    return v;
}

// ---------------- positional softmax ----------------
__global__ void __launch_bounds__(256) pos_kernel(
    const float* __restrict__ coords, const float* __restrict__ pe, float* __restrict__ Q)
{
    __shared__ float pesh[6];
    __shared__ float red[8], red2[8];
    const int p = blockIdx.x;
    const int tid = threadIdx.x;
    if (tid < 6) pesh[tid] = pe[p * 6 + tid];
    __syncthreads();

    const float* cbase = coords + (size_t)p * N_ * 6;
    float z[4];
#pragma unroll
    for (int i = 0; i < 4; i++) {
        const float* c = cbase + (size_t)(i * 256 + tid) * 6;
        float2 c01 = *(const float2*)(c);
        float2 c23 = *(const float2*)(c + 2);
        float2 c45 = *(const float2*)(c + 4);
        z[i] = c01.x * pesh[0] + c01.y * pesh[1] + c23.x * pesh[2]
             + c23.y * pesh[3] + c45.x * pesh[4] + c45.y * pesh[5];
    }
    float m = fmaxf(fmaxf(z[0], z[1]), fmaxf(z[2], z[3]));
    m = warpMax(m);
    if ((tid & 31) == 0) red[tid >> 5] = m;
    __syncthreads();
    m = red[0];
#pragma unroll
    for (int i = 1; i < 8; i++) m = fmaxf(m, red[i]);

    float e[4], s = 0.f;
#pragma unroll
    for (int i = 0; i < 4; i++) { e[i] = expf(z[i] - m); s += e[i]; }
    s = warpSum(s);
    if ((tid & 31) == 0) red2[tid >> 5] = s;
    __syncthreads();
    s = red2[0];
#pragma unroll
    for (int i = 1; i < 8; i++) s += red2[i];
    const float inv = 1.f / s;
#pragma unroll
    for (int i = 0; i < 4; i++)
        Q[(size_t)p * N_ + i * 256 + tid] = e[i] * inv;
}

// -------- row softmax + gate mix + entropy; warp per row; attn -> bf16 hi/lo --------
__global__ void __launch_bounds__(256) mix_kernel(
    const float* __restrict__ S, const float* __restrict__ Q,
    const float* __restrict__ gating, const float* __restrict__ temp,
    bf16* __restrict__ AH, bf16* __restrict__ AL, float* __restrict__ hmap)
{
    const int row  = blockIdx.x * 8 + (threadIdx.x >> 5);   // b*N + n
    const int lane = threadIdx.x & 31;
    const float4* s4 = (const float4*)(S + (size_t)row * N_);
    const float4* q4 = (const float4*)(Q + (size_t)(row & (N_ - 1)) * N_);

    float4 v[8];
#pragma unroll
    for (int i = 0; i < 8; i++) v[i] = s4[lane + 32 * i];

    float m = -1e30f;
#pragma unroll
    for (int i = 0; i < 8; i++)
        m = fmaxf(m, fmaxf(fmaxf(v[i].x, v[i].y), fmaxf(v[i].z, v[i].w)));
    m = warpMax(m);

    float ssum = 0.f;
#pragma unroll
    for (int i = 0; i < 8; i++) {
        v[i].x = expf(v[i].x - m); v[i].y = expf(v[i].y - m);
        v[i].z = expf(v[i].z - m); v[i].w = expf(v[i].w - m);
        ssum += v[i].x + v[i].y + v[i].z + v[i].w;
    }
    ssum = warpSum(ssum);
    const float inv = 1.f / ssum;

    const float gt = 1.f / (1.f + expf(-gating[0]));
    const float og = 1.f - gt;

    uint2* AH2 = (uint2*)(AH + (size_t)row * N_);
    uint2* AL2 = (uint2*)(AL + (size_t)row * N_);
    float H = 0.f;
#pragma unroll
    for (int i = 0; i < 8; i++) {
        float4 qv = q4[lane + 32 * i];
        float a[4];
        a[0] = og * v[i].x * inv + gt * qv.x;
        a[1] = og * v[i].y * inv + gt * qv.y;
        a[2] = og * v[i].z * inv + gt * qv.z;
        a[3] = og * v[i].w * inv + gt * qv.w;
        H -= a[0] * logf(a[0] + 1e-8f) + a[1] * logf(a[1] + 1e-8f)
           + a[2] * logf(a[2] + 1e-8f) + a[3] * logf(a[3] + 1e-8f);
        bf16 h[4], l[4];
#pragma unroll
        for (int j = 0; j < 4; j++) {
            h[j] = __float2bfloat16_rn(a[j]);
            l[j] = __float2bfloat16_rn(a[j] - __bfloat162float(h[j]));
        }
        AH2[lane + 32 * i] = *(uint2*)h;
        AL2[lane + 32 * i] = *(uint2*)l;
    }
    H = warpSum(H);
    if (lane == 0) {
        const float sig = 1.f / (1.f + expf(-temp[0] * H));
        hmap[row] = 2.f * (1.f - sig);
    }
}

// ---------------- launch ----------------
extern "C" void kernel_launch(void* const* d_in, const int* in_sizes, int n_in,
                              void* d_out, int out_size)
{
    const float* x      = (const float*)d_in[0];
    const float* y      = (const float*)d_in[1];
    const float* coords = (const float*)d_in[2];
    const float* W      = (const float*)d_in[3];
    const float* pe     = (const float*)d_in[4];
    const float* gating = (const float*)d_in[5];
    const float* temp   = (const float*)d_in[6];

    float* out  = (float*)d_out;                // [B,N,D]
    float* hmap = out + (size_t)B_ * N_ * D_;   // [B,N,1]

    float *Sb, *Qb;
    bf16 *xh, *yh, *yl, *wh, *wl, *kh, *kl, *yth, *ytl, *ah, *al;
    cudaGetSymbolAddress((void**)&Sb, g_S);
    cudaGetSymbolAddress((void**)&Qb, g_Q);
    cudaGetSymbolAddress((void**)&xh, g_xh);
    cudaGetSymbolAddress((void**)&yh, g_yh);  cudaGetSymbolAddress((void**)&yl, g_yl);
    cudaGetSymbolAddress((void**)&wh, g_wh);  cudaGetSymbolAddress((void**)&wl, g_wl);
    cudaGetSymbolAddress((void**)&kh, g_kh);  cudaGetSymbolAddress((void**)&kl, g_kl);
    cudaGetSymbolAddress((void**)&yth, g_yth); cudaGetSymbolAddress((void**)&ytl, g_ytl);
    cudaGetSymbolAddress((void**)&ah, g_ah);  cudaGetSymbolAddress((void**)&al, g_al);

    cudaFuncSetAttribute((const void*)gemm_mma<true, 3>,  cudaFuncAttributeMaxDynamicSharedMemorySize, SMEM_BYTES);
    cudaFuncSetAttribute((const void*)gemm_mma<false, 2>, cudaFuncAttributeMaxDynamicSharedMemorySize, SMEM_BYTES);
    cudaFuncSetAttribute((const void*)gemm_mma<false, 3>, cudaFuncAttributeMaxDynamicSharedMemorySize, SMEM_BYTES);

    const int nBND4 = (B_ * N_ * D_) / 4;
    const int nDD4  = (D_ * D_) / 4;

    split_Ty<<<dim3(N_ / 32, D_ / 32, B_), dim3(32, 8)>>>(y, yh, yl, yth, ytl);
    split_h<<<(nBND4 + 255) / 256, 256>>>((const float4*)x, (uint2*)xh, nBND4);
    split_k<<<(nDD4  + 255) / 256, 256>>>((const float4*)W, (uint2*)wh, (uint2*)wl, nDD4);

    pos_kernel<<<N_, 256>>>(coords, pe, Qb);

    // 1) k = y @ W^T  (M=16384, N=768, K=768) -> kh/kl bf16 directly (3-term)
    gemm_mma<true, 3><<<dim3(D_ / 128, (B_ * N_) / 128, 1), 128, SMEM_BYTES>>>(
        yh, yl, wh, wl, nullptr, kh, kl, D_, D_, D_, D_, 0, 0, 0, 1.0f);

    // 2) S = (x @ k^T) * SCALE, batched over B -> fp32 (2-term; xh doubles as unused Al)
    gemm_mma<false, 2><<<dim3(N_ / 128, N_ / 128, B_), 128, SMEM_BYTES>>>(
        xh, xh, kh, kl, Sb, nullptr, nullptr, D_, D_, D_, N_,
        (size_t)N_ * D_, (size_t)N_ * D_, (size_t)N_ * N_, SCALE_);

    // 3) softmax + mix + entropy -> attn bf16 hi/lo + hmap (warp per row)
    mix_kernel<<<(B_ * N_) / 8, 256>>>(Sb, Qb, gating, temp, ah, al, hmap);

    // 4) out = attn @ y (B operand = y^T per batch, K=1024) (3-term: direct output)
    gemm_mma<false, 3><<<dim3(D_ / 128, N_ / 128, B_), 128, SMEM_BYTES>>>(
        ah, al, yth, ytl, out, nullptr, nullptr, N_, N_, N_, D_,
        (size_t)N_ * N_, (size_t)D_ * N_, (size_t)N_ * D_, 1.0f);
}

// round 11
// speedup vs baseline: 1.1001x; 1.0156x over previous
#include <cuda_runtime.h>
#include <cuda_bf16.h>
#include <cstdint>

#define B_ 16
#define N_ 1024
#define D_ 768

typedef __nv_bfloat16 bf16;

static const float SCALE_ = 0.03608439182435161f; // 768^-0.5

// ---------------- scratch (device globals: allocation-free contract) ----------------
__device__ __align__(16) float g_S[(size_t)B_ * N_ * N_];   // 64 MB fp32 scores
__device__ __align__(16) float g_Q[(size_t)N_ * N_];        // 4 MB  pos softmax
__device__ __align__(16) bf16 g_xh[(size_t)B_ * N_ * D_];
__device__ __align__(16) bf16 g_yh[(size_t)B_ * N_ * D_], g_yl[(size_t)B_ * N_ * D_];
__device__ __align__(16) bf16 g_wh[(size_t)D_ * D_],      g_wl[(size_t)D_ * D_];
__device__ __align__(16) bf16 g_kh[(size_t)B_ * N_ * D_], g_kl[(size_t)B_ * N_ * D_];
__device__ __align__(16) bf16 g_yth[(size_t)B_ * D_ * N_], g_ytl[(size_t)B_ * D_ * N_];
__device__ __align__(16) bf16 g_ah[(size_t)B_ * N_ * N_],  g_al[(size_t)B_ * N_ * N_];

// ---------------- helpers ----------------
__device__ __forceinline__ uint32_t smem_u32(const void* p) {
    uint32_t a;
    asm("{ .reg .u64 t; cvta.to.shared.u64 t, %1; cvt.u32.u64 %0, t; }" : "=r"(a) : "l"(p));
    return a;
}
#define CP_COMMIT() asm volatile("cp.async.commit_group;" ::: "memory")

__device__ __forceinline__ void mma16816(float* c, const uint32_t* a, const uint32_t* b) {
    asm volatile(
        "mma.sync.aligned.m16n8k16.row.col.f32.bf16.bf16.f32 "
        "{%0,%1,%2,%3}, {%4,%5,%6,%7}, {%8,%9}, {%0,%1,%2,%3};"
        : "+f"(c[0]), "+f"(c[1]), "+f"(c[2]), "+f"(c[3])
        : "r"(a[0]), "r"(a[1]), "r"(a[2]), "r"(a[3]), "r"(b[0]), "r"(b[1]));
}
__device__ __forceinline__ void ldsm4(uint32_t* r, uint32_t addr) {
    asm volatile("ldmatrix.sync.aligned.m8n8.x4.shared.b16 {%0,%1,%2,%3}, [%4];"
        : "=r"(r[0]), "=r"(r[1]), "=r"(r[2]), "=r"(r[3]) : "r"(addr));
}

// ---------------- HMMA split-bf16 GEMM: C[M,N] = alpha * sum(A*B^T terms) ----------
// A[M,K], B[N,K] row-major, (hi, lo) bf16 pairs. TERMS=3: Ah*Bh + Ah*Bl + Al*Bh
//   (4 tiles/stage, 3 stages). TERMS=2: Ah*Bh + Ah*Bl, Al never touched
//   (compact 3 tiles/stage, 4 stages). Both use 96 KB -> 2 CTAs/SM.
// Block 128x128, K-chunk 32, 4 warps (warp tile 64x64). SMEM XOR-swizzled.
// Single-sync mainloop; fills issued AFTER s=0 ldmatrix.  [FROZEN since R10]
#define TILE_SZ 8192          // 128 * 64
#define SMEM_BYTES 98304      // 96 KB (both variants)

__device__ __forceinline__ void fill_tile(uint32_t dst, const bf16* __restrict__ g,
                                          int ld, int r0, int k0, int tid) {
#pragma unroll
    for (int it = 0; it < 4; it++) {
        int idx = it * 128 + tid;
        int r = idx >> 2, b = idx & 3;
        uint32_t sw = (uint32_t)(r * 64 + ((b ^ ((r >> 1) & 3)) * 16));
        const bf16* src = g + (size_t)(r0 + r) * ld + k0 + b * 8;
        asm volatile("cp.async.cg.shared.global [%0], [%1], 16;"
                     :: "r"(dst + sw), "l"(src));
    }
}

template <int TERMS>
__device__ __forceinline__ void fill_chunk(uint32_t S0,
                                           const bf16* Ah_, const bf16* Al_,
                                           const bf16* Bh_, const bf16* Bl_,
                                           int lda, int ldb, int m0, int n0, int k0, int tid) {
    constexpr int BH = (TERMS == 3) ? 2 : 1;
    fill_tile(S0 + 0 * TILE_SZ, Ah_, lda, m0, k0, tid);
    if (TERMS == 3) fill_tile(S0 + 1 * TILE_SZ, Al_, lda, m0, k0, tid);
    fill_tile(S0 + BH * TILE_SZ,       Bh_, ldb, n0, k0, tid);
    fill_tile(S0 + (BH + 1) * TILE_SZ, Bl_, ldb, n0, k0, tid);
}

template <bool SPLIT_OUT, int TERMS>
__global__ void __launch_bounds__(128, 2) gemm_mma(
    const bf16* __restrict__ Ah_, const bf16* __restrict__ Al_,
    const bf16* __restrict__ Bh_, const bf16* __restrict__ Bl_,
    float* __restrict__ C, bf16* __restrict__ Ch, bf16* __restrict__ Cl,
    int K, int lda, int ldb, int ldc,
    size_t sA, size_t sB, size_t sC, float alpha)
{
    constexpr int NST = (TERMS == 3) ? 3 : 4;
    constexpr int STG = ((TERMS == 3) ? 4 : 3) * TILE_SZ;
    constexpr int BH  = (TERMS == 3) ? 2 : 1;

    extern __shared__ char sm[];
    const uint32_t sb = smem_u32(sm);
    const int tid = threadIdx.x, lane = tid & 31, w = tid >> 5;
    const int wm = w & 1, wn = w >> 1;          // warp grid 2(M) x 2(N)
    const int g = lane >> 2, tig = lane & 3;
    const int m0 = blockIdx.y * 128, n0 = blockIdx.x * 128;

    Ah_ += (size_t)blockIdx.z * sA; Al_ += (size_t)blockIdx.z * sA;
    Bh_ += (size_t)blockIdx.z * sB; Bl_ += (size_t)blockIdx.z * sB;

    // ldmatrix lane addressing with swizzle.
    const int rowA = wm * 64 + (lane & 7) + (lane & 8);
    const int hA = (lane >> 4) & 1;
    const int xA = (rowA >> 1) & 3;
    const uint32_t aRow = (uint32_t)(rowA * 64);
    const uint32_t aBlk0 = (uint32_t)(((0 + hA) ^ xA) * 16);
    const uint32_t aBlk1 = (uint32_t)(((2 + hA) ^ xA) * 16);
    const int rowB = wn * 64 + (lane & 7) + ((lane & 16) >> 1);
    const int hB = (lane >> 3) & 1;
    const int xB = (rowB >> 1) & 3;
    const uint32_t bRow = (uint32_t)(rowB * 64);
    const uint32_t bBlk0 = (uint32_t)(((0 + hB) ^ xB) * 16);
    const uint32_t bBlk1 = (uint32_t)(((2 + hB) ^ xB) * 16);

    float acc[4][8][4];
#pragma unroll
    for (int i = 0; i < 4; i++)
#pragma unroll
        for (int j = 0; j < 8; j++)
#pragma unroll
            for (int c = 0; c < 4; c++) acc[i][j][c] = 0.f;

    const int KT = K >> 5;

    // prologue: fill all NST stages (chunks 0..NST-1)
#pragma unroll
    for (int p = 0; p < NST; p++) {
        fill_chunk<TERMS>(sb + p * STG, Ah_, Al_, Bh_, Bl_, lda, ldb, m0, n0, p * 32, tid);
        CP_COMMIT();
    }

    for (int kt = 0; kt < KT; ++kt) {
        asm volatile("cp.async.wait_group %0;" :: "n"(NST - 2) : "memory");
        __syncthreads();
        const uint32_t S0 = sb + (kt % NST) * STG;
        const uint32_t pAh = S0, pAl = S0 + TILE_SZ;
        const uint32_t pBh = S0 + BH * TILE_SZ, pBl = S0 + (BH + 1) * TILE_SZ;

        // ---- s = 0: fragment loads FIRST ----
        uint32_t ah[4][4], al[4][4], bh[8][2], bl[8][2];
#pragma unroll
        for (int mf = 0; mf < 4; mf++) {
            ldsm4(&ah[mf][0], pAh + aRow + mf * 1024 + aBlk0);
            if (TERMS == 3) ldsm4(&al[mf][0], pAl + aRow + mf * 1024 + aBlk0);
        }
#pragma unroll
        for (int p = 0; p < 4; p++) {
            ldsm4(&bh[2 * p][0], pBh + bRow + p * 1024 + bBlk0);
            ldsm4(&bl[2 * p][0], pBl + bRow + p * 1024 + bBlk0);
        }
        if (kt >= 1) {
            if (kt + NST - 1 < KT)
                fill_chunk<TERMS>(sb + ((kt + NST - 1) % NST) * STG,
                                  Ah_, Al_, Bh_, Bl_, lda, ldb, m0, n0,
                                  (kt + NST - 1) * 32, tid);
            CP_COMMIT();
        }
#pragma unroll
        for (int mf = 0; mf < 4; mf++)
#pragma unroll
            for (int nf = 0; nf < 8; nf++)
                mma16816(acc[mf][nf], ah[mf], bh[nf]);
#pragma unroll
        for (int mf = 0; mf < 4; mf++)
#pragma unroll
            for (int nf = 0; nf < 8; nf++)
                mma16816(acc[mf][nf], ah[mf], bl[nf]);
        if (TERMS == 3) {
#pragma unroll
            for (int mf = 0; mf < 4; mf++)
#pragma unroll
                for (int nf = 0; nf < 8; nf++)
                    mma16816(acc[mf][nf], al[mf], bh[nf]);
        }

        // ---- s = 1 ----
#pragma unroll
        for (int mf = 0; mf < 4; mf++) {
            ldsm4(&ah[mf][0], pAh + aRow + mf * 1024 + aBlk1);
            if (TERMS == 3) ldsm4(&al[mf][0], pAl + aRow + mf * 1024 + aBlk1);
        }
#pragma unroll
        for (int p = 0; p < 4; p++) {
            ldsm4(&bh[2 * p][0], pBh + bRow + p * 1024 + bBlk1);
            ldsm4(&bl[2 * p][0], pBl + bRow + p * 1024 + bBlk1);
        }
#pragma unroll
        for (int mf = 0; mf < 4; mf++)
#pragma unroll
            for (int nf = 0; nf < 8; nf++)
                mma16816(acc[mf][nf], ah[mf], bh[nf]);
#pragma unroll
        for (int mf = 0; mf < 4; mf++)
#pragma unroll
            for (int nf = 0; nf < 8; nf++)
                mma16816(acc[mf][nf], ah[mf], bl[nf]);
        if (TERMS == 3) {
#pragma unroll
            for (int mf = 0; mf < 4; mf++)
#pragma unroll
                for (int nf = 0; nf < 8; nf++)
                    mma16816(acc[mf][nf], al[mf], bh[nf]);
        }
    }

    // epilogue
#pragma unroll
    for (int mf = 0; mf < 4; mf++) {
#pragma unroll
        for (int nf = 0; nf < 8; nf++) {
            const int row = m0 + wm * 64 + mf * 16 + g;
            const int col = n0 + wn * 64 + nf * 8 + tig * 2;
            float c0 = acc[mf][nf][0] * alpha, c1 = acc[mf][nf][1] * alpha;
            float c2 = acc[mf][nf][2] * alpha, c3 = acc[mf][nf][3] * alpha;
            if (SPLIT_OUT) {
                bf16 h0 = __float2bfloat16_rn(c0), h1 = __float2bfloat16_rn(c1);
                bf16 h2 = __float2bfloat16_rn(c2), h3 = __float2bfloat16_rn(c3);
                bf16 l0 = __float2bfloat16_rn(c0 - __bfloat162float(h0));
                bf16 l1 = __float2bfloat16_rn(c1 - __bfloat162float(h1));
                bf16 l2 = __float2bfloat16_rn(c2 - __bfloat162float(h2));
                bf16 l3 = __float2bfloat16_rn(c3 - __bfloat162float(h3));
                bf16 ph0[2] = {h0, h1}, ph2[2] = {h2, h3};
                bf16 pl0[2] = {l0, l1}, pl2[2] = {l2, l3};
                *(uint32_t*)&Ch[(size_t)row * ldc + col]       = *(uint32_t*)ph0;
                *(uint32_t*)&Ch[(size_t)(row + 8) * ldc + col] = *(uint32_t*)ph2;
                *(uint32_t*)&Cl[(size_t)row * ldc + col]       = *(uint32_t*)pl0;
                *(uint32_t*)&Cl[(size_t)(row + 8) * ldc + col] = *(uint32_t*)pl2;
            } else {
                float* Cp = C + (size_t)blockIdx.z * sC;
                float2 v0 = {c0, c1}, v2 = {c2, c3};
                *(float2*)&Cp[(size_t)row * ldc + col]       = v0;
                *(float2*)&Cp[(size_t)(row + 8) * ldc + col] = v2;
            }
        }
    }
}

// ---------------- fp32 -> (hi,lo) bf16 split ----------------
__global__ void __launch_bounds__(256) split_k(const float4* __restrict__ in,
                                               uint2* __restrict__ hi, uint2* __restrict__ lo,
                                               int n4) {
    int i = blockIdx.x * 256 + threadIdx.x;
    if (i >= n4) return;
    float4 v = in[i];
    float xs[4] = {v.x, v.y, v.z, v.w};
    bf16 h[4], l[4];
#pragma unroll
    for (int j = 0; j < 4; j++) {
        h[j] = __float2bfloat16_rn(xs[j]);
        l[j] = __float2bfloat16_rn(xs[j] - __bfloat162float(h[j]));
    }
    hi[i] = *(uint2*)h;
    lo[i] = *(uint2*)l;
}

// ---------------- fp32 -> hi bf16 only ----------------
__global__ void __launch_bounds__(256) split_h(const float4* __restrict__ in,
                                               uint2* __restrict__ hi, int n4) {
    int i = blockIdx.x * 256 + threadIdx.x;
    if (i >= n4) return;
    float4 v = in[i];
    float xs[4] = {v.x, v.y, v.z, v.w};
    bf16 h[4];
#pragma unroll
    for (int j = 0; j < 4; j++) h[j] = __float2bfloat16_rn(xs[j]);
    hi[i] = *(uint2*)h;
}

// ------- y [B,N,D]: split to yh/yl AND transposed yth/ytl [B,D,N] in one pass -------
__global__ void __launch_bounds__(256) split_Ty(const float* __restrict__ y,
                                                bf16* __restrict__ yh, bf16* __restrict__ yl,
                                                bf16* __restrict__ th, bf16* __restrict__ tl) {
    __shared__ float t[32][33];
    const int b = blockIdx.z;
    const float* Y = y + (size_t)b * N_ * D_;
    const int n0 = blockIdx.x * 32, d0 = blockIdx.y * 32;
    const int tx = threadIdx.x, ty = threadIdx.y;  // (32, 8)
    bf16* YH = yh + (size_t)b * N_ * D_;
    bf16* YL = yl + (size_t)b * N_ * D_;
#pragma unroll
    for (int i = 0; i < 4; i++) {
        const int r = ty + i * 8;
        const float v = Y[(size_t)(n0 + r) * D_ + d0 + tx];
        t[r][tx] = v;
        bf16 h = __float2bfloat16_rn(v);
        YH[(size_t)(n0 + r) * D_ + d0 + tx] = h;
        YL[(size_t)(n0 + r) * D_ + d0 + tx] = __float2bfloat16_rn(v - __bfloat162float(h));
    }
    __syncthreads();
    bf16* TH = th + (size_t)b * D_ * N_;
    bf16* TL = tl + (size_t)b * D_ * N_;
#pragma unroll
    for (int i = 0; i < 4; i++) {
        int r = ty + i * 8;
        float v = t[tx][r];
        bf16 h = __float2bfloat16_rn(v);
        TH[(size_t)(d0 + r) * N_ + n0 + tx] = h;
        TL[(size_t)(d0 + r) * N_ + n0 + tx] = __float2bfloat16_rn(v - __bfloat162float(h));
    }
}

// ---------------- reductions ----------------
__device__ __forceinline__ float warpMax(float v) {
#pragma unroll
    for (int o = 16; o; o >>= 1) v = fmaxf(v, __shfl_xor_sync(0xffffffffu, v, o));
    return v;
}
__device__ __forceinline__ float warpSum(float v) {
#pragma unroll
    for (int o = 16; o; o >>= 1) v += __shfl_xor_sync(0xffffffffu, v, o);
    return v;
}

// ---------------- positional softmax ----------------
__global__ void __launch_bounds__(256) pos_kernel(
    const float* __restrict__ coords, const float* __restrict__ pe, float* __restrict__ Q)
{
    __shared__ float pesh[6];
    __shared__ float red[8], red2[8];
    const int p = blockIdx.x;
    const int tid = threadIdx.x;
    if (tid < 6) pesh[tid] = pe[p * 6 + tid];
    __syncthreads();

    const float* cbase = coords + (size_t)p * N_ * 6;
    float z[4];
#pragma unroll
    for (int i = 0; i < 4; i++) {
        const float* c = cbase + (size_t)(i * 256 + tid) * 6;
        float2 c01 = *(const float2*)(c);
        float2 c23 = *(const float2*)(c + 2);
        float2 c45 = *(const float2*)(c + 4);
        z[i] = c01.x * pesh[0] + c01.y * pesh[1] + c23.x * pesh[2]
             + c23.y * pesh[3] + c45.x * pesh[4] + c45.y * pesh[5];
    }
    float m = fmaxf(fmaxf(z[0], z[1]), fmaxf(z[2], z[3]));
    m = warpMax(m);
    if ((tid & 31) == 0) red[tid >> 5] = m;
    __syncthreads();
    m = red[0];
#pragma unroll
    for (int i = 1; i < 8; i++) m = fmaxf(m, red[i]);

    float e[4], s = 0.f;
#pragma unroll
    for (int i = 0; i < 4; i++) { e[i] = __expf(z[i] - m); s += e[i]; }
    s = warpSum(s);
    if ((tid & 31) == 0) red2[tid >> 5] = s;
    __syncthreads();
    s = red2[0];
#pragma unroll
    for (int i = 1; i < 8; i++) s += red2[i];
    const float inv = 1.f / s;
#pragma unroll
    for (int i = 0; i < 4; i++)
        Q[(size_t)p * N_ + i * 256 + tid] = e[i] * inv;
}

// -------- row softmax + gate mix + entropy; warp per row; fast transcendentals -----
__global__ void __launch_bounds__(256) mix_kernel(
    const float* __restrict__ S, const float* __restrict__ Q,
    const float* __restrict__ gating, const float* __restrict__ temp,
    bf16* __restrict__ AH, bf16* __restrict__ AL, float* __restrict__ hmap)
{
    const int row  = blockIdx.x * 8 + (threadIdx.x >> 5);   // b*N + n
    const int lane = threadIdx.x & 31;
    const float4* s4 = (const float4*)(S + (size_t)row * N_);
    const float4* q4 = (const float4*)(Q + (size_t)(row & (N_ - 1)) * N_);

    float4 v[8];
#pragma unroll
    for (int i = 0; i < 8; i++) v[i] = s4[lane + 32 * i];

    float m = -1e30f;
#pragma unroll
    for (int i = 0; i < 8; i++)
        m = fmaxf(m, fmaxf(fmaxf(v[i].x, v[i].y), fmaxf(v[i].z, v[i].w)));
    m = warpMax(m);

    float ssum = 0.f;
#pragma unroll
    for (int i = 0; i < 8; i++) {
        v[i].x = __expf(v[i].x - m); v[i].y = __expf(v[i].y - m);
        v[i].z = __expf(v[i].z - m); v[i].w = __expf(v[i].w - m);
        ssum += v[i].x + v[i].y + v[i].z + v[i].w;
    }
    ssum = warpSum(ssum);
    const float inv = 1.f / ssum;

    const float gt = 1.f / (1.f + __expf(-gating[0]));
    const float og = 1.f - gt;

    uint2* AH2 = (uint2*)(AH + (size_t)row * N_);
    uint2* AL2 = (uint2*)(AL + (size_t)row * N_);
    float H = 0.f;
#pragma unroll
    for (int i = 0; i < 8; i++) {
        float4 qv = q4[lane + 32 * i];
        float a[4];
        a[0] = og * v[i].x * inv + gt * qv.x;
        a[1] = og * v[i].y * inv + gt * qv.y;
        a[2] = og * v[i].z * inv + gt * qv.z;
        a[3] = og * v[i].w * inv + gt * qv.w;
        H -= a[0] * __logf(a[0] + 1e-8f) + a[1] * __logf(a[1] + 1e-8f)
           + a[2] * __logf(a[2] + 1e-8f) + a[3] * __logf(a[3] + 1e-8f);
        bf16 h[4], l[4];
#pragma unroll
        for (int j = 0; j < 4; j++) {
            h[j] = __float2bfloat16_rn(a[j]);
            l[j] = __float2bfloat16_rn(a[j] - __bfloat162float(h[j]));
        }
        AH2[lane + 32 * i] = *(uint2*)h;
        AL2[lane + 32 * i] = *(uint2*)l;
    }
    H = warpSum(H);
    if (lane == 0) {
        const float sig = 1.f / (1.f + __expf(-temp[0] * H));
        hmap[row] = 2.f * (1.f - sig);
    }
}

// ---------------- launch ----------------
extern "C" void kernel_launch(void* const* d_in, const int* in_sizes, int n_in,
                              void* d_out, int out_size)
{
    const float* x      = (const float*)d_in[0];
    const float* y      = (const float*)d_in[1];
    const float* coords = (const float*)d_in[2];
    const float* W      = (const float*)d_in[3];
    const float* pe     = (const float*)d_in[4];
    const float* gating = (const float*)d_in[5];
    const float* temp   = (const float*)d_in[6];

    float* out  = (float*)d_out;                // [B,N,D]
    float* hmap = out + (size_t)B_ * N_ * D_;   // [B,N,1]

    float *Sb, *Qb;
    bf16 *xh, *yh, *yl, *wh, *wl, *kh, *kl, *yth, *ytl, *ah, *al;
    cudaGetSymbolAddress((void**)&Sb, g_S);
    cudaGetSymbolAddress((void**)&Qb, g_Q);
    cudaGetSymbolAddress((void**)&xh, g_xh);
    cudaGetSymbolAddress((void**)&yh, g_yh);  cudaGetSymbolAddress((void**)&yl, g_yl);
    cudaGetSymbolAddress((void**)&wh, g_wh);  cudaGetSymbolAddress((void**)&wl, g_wl);
    cudaGetSymbolAddress((void**)&kh, g_kh);  cudaGetSymbolAddress((void**)&kl, g_kl);
    cudaGetSymbolAddress((void**)&yth, g_yth); cudaGetSymbolAddress((void**)&ytl, g_ytl);
    cudaGetSymbolAddress((void**)&ah, g_ah);  cudaGetSymbolAddress((void**)&al, g_al);

    cudaFuncSetAttribute((const void*)gemm_mma<true, 3>,  cudaFuncAttributeMaxDynamicSharedMemorySize, SMEM_BYTES);
    cudaFuncSetAttribute((const void*)gemm_mma<false, 2>, cudaFuncAttributeMaxDynamicSharedMemorySize, SMEM_BYTES);
    cudaFuncSetAttribute((const void*)gemm_mma<false, 3>, cudaFuncAttributeMaxDynamicSharedMemorySize, SMEM_BYTES);

    const int nBND4 = (B_ * N_ * D_) / 4;
    const int nDD4  = (D_ * D_) / 4;

    split_Ty<<<dim3(N_ / 32, D_ / 32, B_), dim3(32, 8)>>>(y, yh, yl, yth, ytl);
    split_h<<<(nBND4 + 255) / 256, 256>>>((const float4*)x, (uint2*)xh, nBND4);
    split_k<<<(nDD4  + 255) / 256, 256>>>((const float4*)W, (uint2*)wh, (uint2*)wl, nDD4);

    pos_kernel<<<N_, 256>>>(coords, pe, Qb);

    // 1) k = y @ W^T  (M=16384, N=768, K=768) -> kh/kl bf16 directly (3-term)
    gemm_mma<true, 3><<<dim3(D_ / 128, (B_ * N_) / 128, 1), 128, SMEM_BYTES>>>(
        yh, yl, wh, wl, nullptr, kh, kl, D_, D_, D_, D_, 0, 0, 0, 1.0f);

    // 2) S = (x @ k^T) * SCALE, batched over B -> fp32 (2-term; xh doubles as unused Al)
    gemm_mma<false, 2><<<dim3(N_ / 128, N_ / 128, B_), 128, SMEM_BYTES>>>(
        xh, xh, kh, kl, Sb, nullptr, nullptr, D_, D_, D_, N_,
        (size_t)N_ * D_, (size_t)N_ * D_, (size_t)N_ * N_, SCALE_);

    // 3) softmax + mix + entropy -> attn bf16 hi/lo + hmap (warp per row)
    mix_kernel<<<(B_ * N_) / 8, 256>>>(Sb, Qb, gating, temp, ah, al, hmap);

    // 4) out = attn @ y (B operand = y^T per batch, K=1024) (3-term: direct output)
    gemm_mma<false, 3><<<dim3(D_ / 128, N_ / 128, B_), 128, SMEM_BYTES>>>(
        ah, al, yth, ytl, out, nullptr, nullptr, N_, N_, N_, D_,
        (size_t)N_ * N_, (size_t)D_ * N_, (size_t)N_ * D_, 1.0f);
}